// round 16
// baseline (speedup 1.0000x reference)
#include <cuda_runtime.h>
#include <cstdint>

// dims (4,4,32,256,256) fp32 -> BC=16 volumes of DD*HH*WW
#define DD 32
#define HH 256
#define WW 256
#define NR 4            // rows per plane (2 outputs + 2 halo)
#define ZT 8            // output planes per z-chunk
#define XSEG 128        // x-width per warp (32 lanes x float4)
#define PLANE (HH * WW)
#define ROWF 136        // floats per smem row: [0..2]pad [3]Lseam [4..131]main [132]Rseam [133..135]pad
#define NSTG 4          // ring stages (prefetch distance 2)
#define STAGEF (NR * ROWF)

__device__ __forceinline__ float4 f4max(float4 a, float4 b) {
    return make_float4(fmaxf(a.x, b.x), fmaxf(a.y, b.y),
                       fmaxf(a.z, b.z), fmaxf(a.w, b.w));
}
__device__ __forceinline__ void cp16(uint32_t d, const float* s) {
    asm volatile("cp.async.cg.shared.global [%0], [%1], 16;" :: "r"(d), "l"(s));
}
__device__ __forceinline__ void cp4(uint32_t d, const float* s) {
    asm volatile("cp.async.ca.shared.global [%0], [%1], 4;" :: "r"(d), "l"(s));
}
__device__ __forceinline__ void cp_commit() {
    asm volatile("cp.async.commit_group;");
}
__device__ __forceinline__ void cp_wait1() {
    asm volatile("cp.async.wait_group 1;");
}
__device__ __forceinline__ void cp_wait2() {
    asm volatile("cp.async.wait_group 2;");
}

__global__ __launch_bounds__(128, 6)
void nms3d_kernel(const float* __restrict__ in, float* __restrict__ out) {
    __shared__ float ring[4][NSTG][NR][ROWF];   // per-warp private slabs

    const int wib  = threadIdx.x >> 5;
    const int lane = threadIdx.x & 31;
    const int gw   = blockIdx.x * 4 + wib;

    // 1b xseg | 7b ytile | 2b zchunk | 4b bc = 16384 warp tiles
    const int xs = (gw & 1) * XSEG;
    const int y0 = ((gw >> 1) & 127) * 2;
    const int z0 = ((gw >> 8) & 3) * ZT;
    const int bc = gw >> 10;
    const int x0 = xs + 4 * lane;

    const float* vol    = in  + (size_t)bc * (DD * PLANE);
    float*       ovol   = out + (size_t)bc * (DD * PLANE);
    const float* baseC  = vol + x0;
    float*       obaseC = ovol + x0;
    const bool l0  = (lane == 0);
    const bool l31 = (lane == 31);
    const bool lseam = l0 || l31;
    const float* baseE  = vol + (l31 ? min(xs + XSEG, WW - 1) : max(xs - 1, 0));

    float* myring = &ring[wib][0][0][0];
    const uint32_t rbase = (uint32_t)__cvta_generic_to_shared(myring);
    const uint32_t dmain = 16 + 16 * lane;            // byte off of main quad in row
    const uint32_t dseam = l31 ? 132 * 4 : 3 * 4;     // byte off of my seam slot
    const int      imain = 4 + 4 * lane;              // float idx of main quad
    const int      iseam = l31 ? 132 : 3;

    int yoff[NR];
#pragma unroll
    for (int r = 0; r < NR; ++r) {
        int y = y0 - 1 + r; y = min(max(y, 0), HH - 1);
        yoff[r] = y * WW;
    }

    // output masks: row edge * x edge
    const float mx0 = (x0 == 0) ? 0.0f : 1.0f;
    const float mx3 = (x0 + 3 == WW - 1) ? 0.0f : 1.0f;
    const float fr0 = (y0 == 0) ? 0.0f : 1.0f;
    const float fr1 = (y0 + 1 == HH - 1) ? 0.0f : 1.0f;

    float4 VA[2], VB[2], MPC[2];

    // async-copy plane Z (z-clamped) into ring stage ST; one commit group
#define PREFZ(Z, ST)                                                          \
    do {                                                                      \
        int zz = (Z); zz = min(max(zz, 0), DD - 1);                           \
        const float* srcC = baseC + (size_t)zz * PLANE;                       \
        const uint32_t sb = rbase + (ST) * (STAGEF * 4);                      \
        _Pragma("unroll")                                                     \
        for (int r = 0; r < NR; ++r)                                          \
            cp16(sb + r * (ROWF * 4) + dmain, srcC + yoff[r]);                \
        if (lseam) {                                                          \
            const float* srcE = baseE + (size_t)zz * PLANE;                   \
            _Pragma("unroll")                                                 \
            for (int r = 0; r < NR; ++r)                                      \
                cp4(sb + r * (ROWF * 4) + dseam, srcE + yoff[r]);             \
        }                                                                     \
    } while (0)

    // consume stage ST: VF[j] = 3x3 xy-window max; SZ[j] = center 8-nb max
#define RMAX(ST, VF, SZ, DOSZ)                                                \
    do {                                                                      \
        const float* st = myring + (ST) * STAGEF;                             \
        float4 m3r[NR]; float4 m2r1, m2r2;                                    \
        _Pragma("unroll")                                                     \
        for (int r = 0; r < NR; ++r) {                                        \
            float4 w  = *(const float4*)(st + r * ROWF + imain);              \
            float eS  = st[r * ROWF + iseam];                                 \
            float wm1 = __shfl_up_sync(0xffffffffu, w.w, 1);                  \
            if (l0)  wm1 = eS;                                                \
            float w4  = __shfl_down_sync(0xffffffffu, w.x, 1);                \
            if (l31) w4 = eS;                                                 \
            float p01 = fmaxf(w.x, w.y);                                      \
            float p12 = fmaxf(w.y, w.z);                                      \
            float p23 = fmaxf(w.z, w.w);                                      \
            m3r[r] = make_float4(fmaxf(wm1, p01), fmaxf(p01, w.z),            \
                                 fmaxf(p12, w.w), fmaxf(p23, w4));            \
            if (DOSZ && r == 1)                                               \
                m2r1 = make_float4(fmaxf(wm1, w.y), fmaxf(w.x, w.z),          \
                                   fmaxf(w.y, w.w), fmaxf(w.z, w4));          \
            if (DOSZ && r == 2)                                               \
                m2r2 = make_float4(fmaxf(wm1, w.y), fmaxf(w.x, w.z),          \
                                   fmaxf(w.y, w.w), fmaxf(w.z, w4));          \
        }                                                                     \
        VF[0] = f4max(f4max(m3r[0], m3r[1]), m3r[2]);                         \
        VF[1] = f4max(f4max(m3r[1], m3r[2]), m3r[3]);                         \
        if (DOSZ) {                                                           \
            SZ[0] = f4max(f4max(m3r[0], m2r1), m3r[2]);                       \
            SZ[1] = f4max(f4max(m3r[1], m2r2), m3r[3]);                       \
        }                                                                     \
    } while (0)

    // step i: emit plane zo=z0+i.
    //   stage (i+1)&3 holds plane zo   (centers read from smem, no WAR: that
    //                                   stage is overwritten only at step i+1)
    //   stage (i+2)&3 holds plane zo+1 (group completed by this step's wait)
    //   stage  i&3    gets plane zo+3  (consumed at step i+2 -> distance 2)
#define STEP(i, VF, VP)                                                       \
    do {                                                                      \
        const int zo = z0 + (i);                                              \
        const size_t zoffC = (size_t)zo * PLANE;                              \
        const float* stc = myring + ((i + 1) & 3) * STAGEF;                   \
        float4 c0 = *(const float4*)(stc + 1 * ROWF + imain);                 \
        float4 c1 = *(const float4*)(stc + 2 * ROWF + imain);                 \
        cp_wait1();                                                           \
        __syncwarp();                                                         \
        float4 szcf[2];                                                       \
        RMAX(((i) + 2) & 3, VF, szcf, 1);                                     \
        if ((i) < ZT - 2) PREFZ(z0 + (i) + 3, (i) & 3);                       \
        cp_commit();                                                          \
        if ((zo == 0) || (zo == DD - 1)) {                                    \
            float4 zq = make_float4(0.f, 0.f, 0.f, 0.f);                      \
            *(float4*)(obaseC + zoffC + yoff[1]) = zq;                        \
            *(float4*)(obaseC + zoffC + yoff[2]) = zq;                        \
        } else {                                                              \
            float4 M0 = f4max(MPC[0], VF[0]);                                 \
            float4 M1 = f4max(MPC[1], VF[1]);                                 \
            float4 o0, o1;                                                    \
            o0.x = ((c0.x > M0.x) ? c0.x : 0.0f) * fr0 * mx0;                 \
            o0.y = ((c0.y > M0.y) ? c0.y : 0.0f) * fr0;                       \
            o0.z = ((c0.z > M0.z) ? c0.z : 0.0f) * fr0;                       \
            o0.w = ((c0.w > M0.w) ? c0.w : 0.0f) * fr0 * mx3;                 \
            o1.x = ((c1.x > M1.x) ? c1.x : 0.0f) * fr1 * mx0;                 \
            o1.y = ((c1.y > M1.y) ? c1.y : 0.0f) * fr1;                       \
            o1.z = ((c1.z > M1.z) ? c1.z : 0.0f) * fr1;                       \
            o1.w = ((c1.w > M1.w) ? c1.w : 0.0f) * fr1 * mx3;                 \
            *(float4*)(obaseC + zoffC + yoff[1]) = o0;                        \
            *(float4*)(obaseC + zoffC + yoff[2]) = o1;                        \
        }                                                                     \
        MPC[0] = f4max(VP[0], szcf[0]);                                       \
        MPC[1] = f4max(VP[1], szcf[1]);                                       \
    } while (0)

    // ---- prologue: 4 planes in flight as 4 groups; wait for first two ----
    {
        PREFZ(z0 - 1, 0); cp_commit();   // g1
        PREFZ(z0,     1); cp_commit();   // g2
        PREFZ(z0 + 1, 2); cp_commit();   // g3
        PREFZ(z0 + 2, 3); cp_commit();   // g4
        cp_wait2();                      // g1,g2 done; g3,g4 pending
        __syncwarp();
        float4 szc0[2];
        RMAX(0, VA, szc0, 0);            // VA = v3[z0-1]
        RMAX(1, VB, szc0, 1);            // VB = v3[z0], szc0 = szc[z0]
        MPC[0] = f4max(VA[0], szc0[0]);
        MPC[1] = f4max(VA[1], szc0[1]);
    }

    // ---- 8 fully-unrolled steps, v3 arrays ping-pong ----
    STEP(0, VA, VB);
    STEP(1, VB, VA);
    STEP(2, VA, VB);
    STEP(3, VB, VA);
    STEP(4, VA, VB);
    STEP(5, VB, VA);
    STEP(6, VA, VB);
    STEP(7, VB, VA);
}

extern "C" void kernel_launch(void* const* d_in, const int* in_sizes, int n_in,
                              void* d_out, int out_size) {
    const float* x = (const float*)d_in[0];
    float* out = (float*)d_out;
    (void)in_sizes; (void)n_in; (void)out_size;
    // 16384 warp-tiles / 4 warps per block
    nms3d_kernel<<<4096, 128>>>(x, out);
}

// round 17
// speedup vs baseline: 1.1255x; 1.1255x over previous
#include <cuda_runtime.h>

// dims (4,4,32,256,256) fp32 -> BC=16 volumes of DD*HH*WW
#define DD 32
#define HH 256
#define WW 256
#define TY 2
#define NR (TY + 2)     // 4 rows (tile + y-halo)
#define ZT 8            // output planes per z-chunk
#define XSEG 128        // x-width per warp (32 lanes x float4)
#define PLANE (HH * WW)

__device__ __forceinline__ float4 f4max(float4 a, float4 b) {
    return make_float4(fmaxf(a.x, b.x), fmaxf(a.y, b.y),
                       fmaxf(a.z, b.z), fmaxf(a.w, b.w));
}

__global__ __launch_bounds__(128, 6)
void nms3d_kernel(const float* __restrict__ in, float* __restrict__ out) {
    const int gw   = blockIdx.x * 4 + (threadIdx.x >> 5);  // global warp-tile id
    const int lane = threadIdx.x & 31;

    // 1b xseg | 7b ytile | 2b zchunk | 4b bc  = 16384 warp tiles
    const int xs = (gw & 1) * XSEG;
    const int y0 = ((gw >> 1) & 127) * TY;
    const int z0 = ((gw >> 8) & 3) * ZT;
    const int bc = gw >> 10;
    const int x0 = xs + 4 * lane;

    const float* vol    = in  + (size_t)bc * (DD * PLANE);
    float*       ovol   = out + (size_t)bc * (DD * PLANE);
    const float* baseC  = vol + x0;
    float*       obaseC = ovol + x0;
    // one edge pointer per lane: lane31 reads the right seam, others the left
    const bool l0  = (lane == 0);
    const bool l31 = (lane == 31);
    const float* baseE  = vol + (l31 ? min(xs + XSEG, WW - 1) : max(xs - 1, 0));

    int yoff[NR];
#pragma unroll
    for (int r = 0; r < NR; ++r) {
        int y = y0 - 1 + r; y = min(max(y, 0), HH - 1);
        yoff[r] = y * WW;
    }

    // output masks: row edge * x edge
    const float mx0 = (x0 == 0) ? 0.0f : 1.0f;
    const float mx3 = (x0 + 3 == WW - 1) ? 0.0f : 1.0f;
    const float fr0 = (y0 == 0) ? 0.0f : 1.0f;
    const float fr1 = (y0 + 1 == HH - 1) ? 0.0f : 1.0f;

    float4 pA[NR], pB[NR];
    float  eA[NR], eB[NR];
    float4 VA[TY], VB[TY], MPC[TY];

    // load plane Z (z-clamped) into buffer P/E
#define PREFZ(Z, P, E)                                                        \
    do {                                                                      \
        int zz = (Z); zz = min(max(zz, 0), DD - 1);                           \
        const size_t zf = (size_t)zz * PLANE;                                 \
        _Pragma("unroll")                                                     \
        for (int r = 0; r < NR; ++r) {                                        \
            P[r] = __ldg((const float4*)(baseC + zf + yoff[r]));              \
            E[r] = __ldg(baseE + zf + yoff[r]);                               \
        }                                                                     \
    } while (0)

    // consume buffer P/E: VF[j] = 3x3 xy-window max; SZ[j] = center 8-nb max
#define RMAX(P, E, VF, SZ, DOSZ)                                              \
    do {                                                                      \
        float4 m3r[NR]; float4 m2r1, m2r2;                                    \
        _Pragma("unroll")                                                     \
        for (int r = 0; r < NR; ++r) {                                        \
            float4 w  = P[r];                                                 \
            float wm1 = __shfl_up_sync(0xffffffffu, w.w, 1);                  \
            if (l0)  wm1 = E[r];                                              \
            float w4  = __shfl_down_sync(0xffffffffu, w.x, 1);                \
            if (l31) w4 = E[r];                                               \
            float p01 = fmaxf(w.x, w.y);                                      \
            float p12 = fmaxf(w.y, w.z);                                      \
            float p23 = fmaxf(w.z, w.w);                                      \
            m3r[r] = make_float4(fmaxf(wm1, p01), fmaxf(p01, w.z),            \
                                 fmaxf(p12, w.w), fmaxf(p23, w4));            \
            if (DOSZ && r == 1)                                               \
                m2r1 = make_float4(fmaxf(wm1, w.y), fmaxf(w.x, w.z),          \
                                   fmaxf(w.y, w.w), fmaxf(w.z, w4));          \
            if (DOSZ && r == 2)                                               \
                m2r2 = make_float4(fmaxf(wm1, w.y), fmaxf(w.x, w.z),          \
                                   fmaxf(w.y, w.w), fmaxf(w.z, w4));          \
        }                                                                     \
        VF[0] = f4max(f4max(m3r[0], m3r[1]), m3r[2]);                         \
        VF[1] = f4max(f4max(m3r[1], m3r[2]), m3r[3]);                         \
        if (DOSZ) {                                                           \
            SZ[0] = f4max(f4max(m3r[0], m2r1), m3r[2]);                       \
            SZ[1] = f4max(f4max(m3r[1], m2r2), m3r[3]);                       \
        }                                                                     \
    } while (0)

    // step i: emit plane zo=z0+i. Buffer P holds plane zo+1 (issued 2 steps
    // ago). Centers of plane zo are re-read via __ldg hoisted to the step top
    // (L1/L2 hit: that line was loaded by this warp 2 steps ago), covered by
    // the RMAX + PREFZ instruction stream before the emit consumes them.
#define STEP(i, P, E, VF, VP)                                                 \
    do {                                                                      \
        const int zo = z0 + (i);                                              \
        const size_t zoffC = (size_t)zo * PLANE;                              \
        float4 c0 = __ldg((const float4*)(baseC + zoffC + yoff[1]));          \
        float4 c1 = __ldg((const float4*)(baseC + zoffC + yoff[2]));          \
        float4 szcf[TY];                                                      \
        RMAX(P, E, VF, szcf, 1);                                              \
        if ((i) < ZT - 2) PREFZ(z0 + (i) + 3, P, E);                          \
        if ((zo == 0) || (zo == DD - 1)) {                                    \
            float4 zq = make_float4(0.f, 0.f, 0.f, 0.f);                      \
            *(float4*)(obaseC + zoffC + yoff[1]) = zq;                        \
            *(float4*)(obaseC + zoffC + yoff[2]) = zq;                        \
        } else {                                                              \
            float4 M0 = f4max(MPC[0], VF[0]);                                 \
            float4 M1 = f4max(MPC[1], VF[1]);                                 \
            float4 o0, o1;                                                    \
            o0.x = ((c0.x > M0.x) ? c0.x : 0.0f) * fr0 * mx0;                 \
            o0.y = ((c0.y > M0.y) ? c0.y : 0.0f) * fr0;                       \
            o0.z = ((c0.z > M0.z) ? c0.z : 0.0f) * fr0;                       \
            o0.w = ((c0.w > M0.w) ? c0.w : 0.0f) * fr0 * mx3;                 \
            o1.x = ((c1.x > M1.x) ? c1.x : 0.0f) * fr1 * mx0;                 \
            o1.y = ((c1.y > M1.y) ? c1.y : 0.0f) * fr1;                       \
            o1.z = ((c1.z > M1.z) ? c1.z : 0.0f) * fr1;                       \
            o1.w = ((c1.w > M1.w) ? c1.w : 0.0f) * fr1 * mx3;                 \
            *(float4*)(obaseC + zoffC + yoff[1]) = o0;                        \
            *(float4*)(obaseC + zoffC + yoff[2]) = o1;                        \
        }                                                                     \
        MPC[0] = f4max(VP[0], szcf[0]);                                       \
        MPC[1] = f4max(VP[1], szcf[1]);                                       \
    } while (0)

    // ---- prologue: both initial planes in flight together ----
    {
        float4 szc0[TY];
        PREFZ(z0 - 1, pA, eA);
        PREFZ(z0,     pB, eB);
        RMAX(pA, eA, VA, szc0, 0);     // VA = v3[z0-1]
        RMAX(pB, eB, VB, szc0, 1);     // VB = v3[z0], szc0 = szc[z0]
        MPC[0] = f4max(VA[0], szc0[0]);
        MPC[1] = f4max(VA[1], szc0[1]);
        PREFZ(z0 + 1, pA, eA);
        PREFZ(z0 + 2, pB, eB);
    }

    // ---- 8 fully-unrolled steps, buffers + v3 arrays ping-pong ----
    STEP(0, pA, eA, VA, VB);
    STEP(1, pB, eB, VB, VA);
    STEP(2, pA, eA, VA, VB);
    STEP(3, pB, eB, VB, VA);
    STEP(4, pA, eA, VA, VB);
    STEP(5, pB, eB, VB, VA);
    STEP(6, pA, eA, VA, VB);
    STEP(7, pB, eB, VB, VA);
}

extern "C" void kernel_launch(void* const* d_in, const int* in_sizes, int n_in,
                              void* d_out, int out_size) {
    const float* x = (const float*)d_in[0];
    float* out = (float*)d_out;
    (void)in_sizes; (void)n_in; (void)out_size;
    // 16384 warp-tiles / 4 warps per block
    nms3d_kernel<<<4096, 128>>>(x, out);
}